// round 17
// baseline (speedup 1.0000x reference)
#include <cuda_runtime.h>
#include <cuda_bf16.h>
#include <cstdint>

#define D        256
#define NMAX     8192
#define BM       128
#define BN       128
#define QBLKS    (NMAX / BM)             // 64
#define KTILES   (NMAX / BN)             // 64
#define TOT_TILES (QBLKS * KTILES)       // 4096
#define GRID_SZ  148                     // one CTA per SM, balanced static ranges
#define THREADS  256                     // 8 warps, warp grid 4(M) x 2(N)
#define SPAD_B   272                     // bytes/row: 256 + 16 pad (68w = 4 mod 32)
#define KSTEPS   8                       // 256 fp8 / 32 per mma

#define LOG2E    1.4426950408889634f
#define LN2      0.6931471805599453f

// smem: [0..31] mbarriers (full0, full1, empty0, empty1), data from 128
#define MB_FULL0   0
#define MB_FULL1   8
#define MB_EMPTY0  16
#define MB_EMPTY1  24
#define DATA_OFF   128
#define TILE_B     (BM * SPAD_B)         // 34816 bytes per tile

__device__ __align__(16) uint8_t g_Qn[(size_t)NMAX * D];   // e4m3
__device__ __align__(16) uint8_t g_Kn[(size_t)NMAX * D];   // e4m3
__device__ float g_psum[NMAX];
__device__ float g_pdiag[NMAX];
__device__ unsigned int g_qb_cnt[QBLKS];   // tiles completed per query block

// ---------------- helpers ----------------
__device__ __forceinline__ void cp_async16(void* smem_dst, const void* gmem_src) {
    uint32_t s = (uint32_t)__cvta_generic_to_shared(smem_dst);
    asm volatile("cp.async.cg.shared.global [%0], [%1], 16;\n" :: "r"(s), "l"(gmem_src));
}
// .noinc: one REAL arrival per thread (init count == #threads).
__device__ __forceinline__ void cp_mbar_arrive_noinc(uint32_t mbar) {
    asm volatile("cp.async.mbarrier.arrive.noinc.shared::cta.b64 [%0];"
                 :: "r"(mbar) : "memory");
}
__device__ __forceinline__ void cp_wait_all() {
    asm volatile("cp.async.wait_group 0;\n" ::: "memory");
}
__device__ __forceinline__ void mbar_init(uint32_t a, uint32_t cnt) {
    asm volatile("mbarrier.init.shared.b64 [%0], %1;" :: "r"(a), "r"(cnt) : "memory");
}
__device__ __forceinline__ void mbar_arrive(uint32_t a) {
    asm volatile("mbarrier.arrive.shared.b64 _, [%0];" :: "r"(a) : "memory");
}
__device__ __forceinline__ void mbar_wait(uint32_t a, uint32_t parity) {
    asm volatile("{\n\t.reg .pred P1;\n\t"
                 "WAIT_LOOP_%=:\n\t"
                 "mbarrier.try_wait.parity.acquire.cta.shared::cta.b64 P1, [%0], %1, 0x989680;\n\t"
                 "@P1 bra.uni WAIT_DONE_%=;\n\t"
                 "bra.uni WAIT_LOOP_%=;\n\t"
                 "WAIT_DONE_%=:\n\t}" :: "r"(a), "r"(parity) : "memory");
}
__device__ __forceinline__ void ldsm_x4(uint32_t& r0, uint32_t& r1,
                                        uint32_t& r2, uint32_t& r3, uint32_t addr) {
    asm volatile("ldmatrix.sync.aligned.m8n8.x4.shared.b16 {%0,%1,%2,%3}, [%4];"
                 : "=r"(r0), "=r"(r1), "=r"(r2), "=r"(r3) : "r"(addr));
}
__device__ __forceinline__ float exp2_fast(float x) {
    float r;
    asm("ex2.approx.ftz.f32 %0, %1;" : "=f"(r) : "f"(x));
    return r;
}

// Load one [128 x 256 fp8] tile into SPAD_B-padded smem via cp.async (256 thr).
__device__ __forceinline__ void load_tile_async(uint8_t* s,
                                                const uint8_t* g, int tid) {
    const uint4* src = (const uint4*)g;
    #pragma unroll
    for (int i = tid; i < BM * 16; i += THREADS) {   // 16 x 16B chunks per row
        int r = i >> 4, c = i & 15;
        cp_async16(s + r * SPAD_B + c * 16, src + r * 16 + c);
    }
}

// ---------------------------------------------------------------------------
// Kernel 1: L2 normalize (one warp per TWO rows) + zero partials/counters/out.
// Queries get 2*log2(e) folded in -> log2-domain logits, no max needed.
// Output in e4m3 (fp8) for the k32 QMMA path.
// ---------------------------------------------------------------------------
__global__ void normalize_kernel(const float* __restrict__ q,
                                 const float* __restrict__ k, int N,
                                 float* __restrict__ out) {
    // zero accumulators + per-qb counters + output (same stream, pre-infonce)
    int gid = blockIdx.x * 256 + threadIdx.x;
    if (gid < NMAX) { g_psum[gid] = 0.f; g_pdiag[gid] = 0.f; }
    if (gid < QBLKS) g_qb_cnt[gid] = 0u;
    if (gid == 0) out[0] = 0.f;

    const int warp = threadIdx.x >> 5, lane = threadIdx.x & 31;
    const int row0 = blockIdx.x * 16 + warp * 2;     // grid = 2N/16
    const bool is_q = row0 < N;
    const int  r0   = is_q ? row0 : row0 - N;
    const float* srcb = is_q ? q : k;
    uint8_t* dstb = is_q ? g_Qn : g_Kn;

    const float4* sA = (const float4*)(srcb + (size_t)r0 * D);
    const float4* sB = (const float4*)(srcb + (size_t)(r0 + 1) * D);
    float4 a0 = sA[lane * 2], a1 = sA[lane * 2 + 1];
    float4 b0 = sB[lane * 2], b1 = sB[lane * 2 + 1];

    float ssA = a0.x*a0.x + a0.y*a0.y + a0.z*a0.z + a0.w*a0.w
              + a1.x*a1.x + a1.y*a1.y + a1.z*a1.z + a1.w*a1.w;
    float ssB = b0.x*b0.x + b0.y*b0.y + b0.z*b0.z + b0.w*b0.w
              + b1.x*b1.x + b1.y*b1.y + b1.z*b1.z + b1.w*b1.w;
    #pragma unroll
    for (int o = 16; o > 0; o >>= 1) {
        ssA += __shfl_xor_sync(0xffffffffu, ssA, o);
        ssB += __shfl_xor_sync(0xffffffffu, ssB, o);
    }

    float scA = rsqrtf(fmaxf(ssA, 1e-24f));
    float scB = rsqrtf(fmaxf(ssB, 1e-24f));
    if (is_q) { scA *= 2.0f * LOG2E; scB *= 2.0f * LOG2E; }

    // pack 8 scaled floats -> 8 e4m3 bytes (4x cvt.rn.satfinite.e4m3x2.f32)
    auto pack8 = [](float4 v0, float4 v1, float sc) -> uint2 {
        uint16_t p0, p1, p2, p3;
        asm("cvt.rn.satfinite.e4m3x2.f32 %0, %1, %2;" : "=h"(p0)
            : "f"(v0.y * sc), "f"(v0.x * sc));
        asm("cvt.rn.satfinite.e4m3x2.f32 %0, %1, %2;" : "=h"(p1)
            : "f"(v0.w * sc), "f"(v0.z * sc));
        asm("cvt.rn.satfinite.e4m3x2.f32 %0, %1, %2;" : "=h"(p2)
            : "f"(v1.y * sc), "f"(v1.x * sc));
        asm("cvt.rn.satfinite.e4m3x2.f32 %0, %1, %2;" : "=h"(p3)
            : "f"(v1.w * sc), "f"(v1.z * sc));
        uint2 o;
        o.x = (uint32_t)p0 | ((uint32_t)p1 << 16);
        o.y = (uint32_t)p2 | ((uint32_t)p3 << 16);
        return o;
    };
    ((uint2*)(dstb + (size_t)r0 * D))[lane]       = pack8(a0, a1, scA);
    ((uint2*)(dstb + (size_t)(r0 + 1) * D))[lane] = pack8(b0, b1, scB);
}

// ---------------------------------------------------------------------------
// Kernel 2: e4m3 mma.sync (m16n8k32, f32 acc) GEMM + fused sum(2^logit) +
// distributed finalize. Same structure as the f16 R16 kernel; ldmatrix
// fragment pattern is byte-identical with "b16 element" = 2 fp8 bytes, so
// only the strides (272B rows, 32B/ks) and the ks count (8) change.
// ---------------------------------------------------------------------------
__global__ __launch_bounds__(THREADS, 1)
void infonce_kernel(float* __restrict__ out) {
    extern __shared__ __align__(16) char smem_raw[];
    const uint32_t sb = (uint32_t)__cvta_generic_to_shared(smem_raw);
    uint8_t* As  = (uint8_t*)(smem_raw + DATA_OFF);  // 128 * SPAD_B
    uint8_t* Bs0 = As + TILE_B;                      // buf 0
    uint8_t* Bs1 = Bs0 + TILE_B;                     // buf 1
    uint8_t* Bbuf[2] = { Bs0, Bs1 };

    const uint32_t full_mb[2]  = { sb + MB_FULL0,  sb + MB_FULL1 };
    const uint32_t empty_mb[2] = { sb + MB_EMPTY0, sb + MB_EMPTY1 };

    const int tid    = threadIdx.x;
    const int lane   = tid & 31;
    const int warp   = tid >> 5;
    const int warp_m = warp >> 1;       // 0..3 (32 rows each)
    const int warp_n = warp & 1;        // 0..1 (64 cols each)

    const int start = (blockIdx.x * TOT_TILES) / GRID_SZ;
    const int end   = ((blockIdx.x + 1) * TOT_TILES) / GRID_SZ;
    int cur_qb = start >> 6;

    if (tid == 0) {
        mbar_init(full_mb[0], THREADS);  mbar_init(full_mb[1], THREADS);
        mbar_init(empty_mb[0], 8);       mbar_init(empty_mb[1], 8);
    }
    __syncthreads();

    // prologue: A(cur_qb) + B(kt(start)) -> buf0
    load_tile_async(As, g_Qn + (size_t)cur_qb * BM * D, tid);
    load_tile_async(Bs0, g_Kn + (size_t)(start & 63) * BN * D, tid);
    cp_mbar_arrive_noinc(full_mb[0]);

    // ldmatrix addresses (byte units; khalf = 16 bytes)
    uint32_t a_base[2];
    #pragma unroll
    for (int mt = 0; mt < 2; ++mt)
        a_base[mt] = (uint32_t)__cvta_generic_to_shared(
            As + (warp_m * 32 + mt * 16 + (lane & 15)) * SPAD_B + (lane >> 4) * 16);
    uint32_t b_row_off[4];                // 4 x 16-row groups = 64 n per warp
    #pragma unroll
    for (int b = 0; b < 4; ++b)
        b_row_off[b] = (uint32_t)(
            (warp_n * 64 + b * 16 + ((lane >> 4) & 1) * 8 + (lane & 7)) * SPAD_B
            + ((lane >> 3) & 1) * 16);

    // parities: full waits start {0,0}; empty waits start {0,1}
    uint32_t cf0 = 0, cf1 = 0, pe0 = 0, pe1 = 1;

    float rsum[4]  = {0.f, 0.f, 0.f, 0.f};
    float rdiag[4] = {0.f, 0.f, 0.f, 0.f};
    __shared__ unsigned int s_last;
    __shared__ float s_wsum[8];

    // flush partials of qb (quad-shfl + atomicAdd + release fence), then zero
    auto flush_partials = [&](int qb) {
        #pragma unroll
        for (int rs = 0; rs < 4; ++rs) {
            rsum[rs]  += __shfl_xor_sync(0xffffffffu, rsum[rs], 1);
            rsum[rs]  += __shfl_xor_sync(0xffffffffu, rsum[rs], 2);
            rdiag[rs] += __shfl_xor_sync(0xffffffffu, rdiag[rs], 1);
            rdiag[rs] += __shfl_xor_sync(0xffffffffu, rdiag[rs], 2);
        }
        if ((lane & 3) == 0) {
            #pragma unroll
            for (int rs = 0; rs < 4; ++rs) {
                int row = qb * BM + warp_m * 32 + (rs >> 1) * 16
                        + (rs & 1) * 8 + (lane >> 2);
                atomicAdd(&g_psum[row], rsum[rs]);
                atomicAdd(&g_pdiag[row], rdiag[rs]);
            }
            __threadfence();      // release: adds visible before counter bump
        }
        #pragma unroll
        for (int rs = 0; rs < 4; ++rs) { rsum[rs] = 0.f; rdiag[rs] = 0.f; }
    };

    // after finishing all our tiles of qb: bump counter; last toucher
    // finalizes that block's 128 rows and adds to out.
    auto finalize_qb = [&](int qb) {
        int lo = qb * KTILES, hi = lo + KTILES;
        int cnt = min(end, hi) - max(start, lo);   // our tiles in this qb (>0)
        __syncthreads();                            // all warps' flush+fence done
        if (tid == 0)
            s_last = (atomicAdd(&g_qb_cnt[qb], (unsigned)cnt) + (unsigned)cnt
                      == (unsigned)KTILES) ? 1u : 0u;
        __syncthreads();
        if (s_last) {
            __threadfence();                        // acquire: see peers' adds
            float v = 0.f;
            if (tid < BM) {
                int r = qb * BM + tid;
                v = LN2 * (log2f(g_psum[r]) - g_pdiag[r]);
            }
            #pragma unroll
            for (int o = 16; o > 0; o >>= 1)
                v += __shfl_xor_sync(0xffffffffu, v, o);
            if (lane == 0) s_wsum[warp] = v;
            __syncthreads();
            if (tid == 0) {
                float tot = 0.f;
                #pragma unroll
                for (int i = 0; i < 8; ++i) tot += s_wsum[i];
                atomicAdd(out, tot / (float)NMAX);
            }
        }
    };

    for (int t = start; t < end; ++t) {
        const int j  = t - start;
        const int qb = t >> 6;
        const int kt = t & 63;
        const int b  = j & 1;
        const int nb = b ^ 1;

        // qb transition (at most once per CTA): flush + finalize, reload A
        if (qb != cur_qb) {
            flush_partials(cur_qb);
            finalize_qb(cur_qb);
            __syncthreads();     // all warps done with MMA on old A
            load_tile_async(As, g_Qn + (size_t)qb * BM * D, tid);
            cp_wait_all();       // A cps (+ any in-flight B(t) cps) complete
            __syncthreads();
            cur_qb = qb;
        }

        // producer: prefetch B of tile t+1 into buf nb
        if (t + 1 < end) {
            uint32_t pe = nb ? pe1 : pe0;
            mbar_wait(empty_mb[nb], pe);
            if (nb) pe1 ^= 1; else pe0 ^= 1;
            load_tile_async(Bbuf[nb],
                            g_Kn + (size_t)((t + 1) & 63) * BN * D, tid);
            cp_mbar_arrive_noinc(full_mb[nb]);
        }

        // consumer: tile t's B (and A) fully visible
        {
            uint32_t cf = b ? cf1 : cf0;
            mbar_wait(full_mb[b], cf);
            if (b) cf1 ^= 1; else cf0 ^= 1;
        }

        float acc[2][8][4];
        #pragma unroll
        for (int a = 0; a < 2; ++a)
            #pragma unroll
            for (int bb2 = 0; bb2 < 8; ++bb2)
                #pragma unroll
                for (int c = 0; c < 4; ++c) acc[a][bb2][c] = 0.f;

        const uint32_t bb = (uint32_t)__cvta_generic_to_shared(Bbuf[b]);

        #pragma unroll
        for (int ks = 0; ks < KSTEPS; ++ks) {        // 8 steps of 32 fp8
            uint32_t af[2][4], bf[16];
            ldsm_x4(af[0][0], af[0][1], af[0][2], af[0][3], a_base[0] + ks * 32);
            ldsm_x4(af[1][0], af[1][1], af[1][2], af[1][3], a_base[1] + ks * 32);
            #pragma unroll
            for (int g = 0; g < 4; ++g)
                ldsm_x4(bf[g * 4], bf[g * 4 + 1], bf[g * 4 + 2], bf[g * 4 + 3],
                        bb + b_row_off[g] + ks * 32);
            #pragma unroll
            for (int mt = 0; mt < 2; ++mt)
                #pragma unroll
                for (int nt = 0; nt < 8; ++nt) {
                    asm volatile(
                        "mma.sync.aligned.m16n8k32.row.col.f32.e4m3.e4m3.f32 "
                        "{%0,%1,%2,%3}, {%4,%5,%6,%7}, {%8,%9}, {%0,%1,%2,%3};\n"
                        : "+f"(acc[mt][nt][0]), "+f"(acc[mt][nt][1]),
                          "+f"(acc[mt][nt][2]), "+f"(acc[mt][nt][3])
                        : "r"(af[mt][0]), "r"(af[mt][1]),
                          "r"(af[mt][2]), "r"(af[mt][3]),
                          "r"(bf[nt * 2]), "r"(bf[nt * 2 + 1]));
                }
        }

        // done reading buf b -> producers may overwrite it (before epilogue)
        if (lane == 0) mbar_arrive(empty_mb[b]);

        // epilogue: 64 ex2 + adds (no max needed in log2 domain)
        #pragma unroll
        for (int mt = 0; mt < 2; ++mt)
            #pragma unroll
            for (int nt = 0; nt < 8; ++nt)
                #pragma unroll
                for (int c = 0; c < 4; ++c)
                    rsum[mt * 2 + (c >> 1)] += exp2_fast(acc[mt][nt][c]);

        // diagonal lives exactly in the kt == qb tile
        if (kt == qb) {
            #pragma unroll
            for (int mt = 0; mt < 2; ++mt)
                #pragma unroll
                for (int nt = 0; nt < 8; ++nt)
                    #pragma unroll
                    for (int c = 0; c < 4; ++c) {
                        int lr = warp_m * 32 + mt * 16 + (c >> 1) * 8 + (lane >> 2);
                        int lc = warp_n * 64 + nt * 8 + (lane & 3) * 2 + (c & 1);
                        if (lr == lc) rdiag[mt * 2 + (c >> 1)] += acc[mt][nt][c];
                    }
        }
    }

    flush_partials(cur_qb);
    finalize_qb(cur_qb);
}

// ---------------------------------------------------------------------------
extern "C" void kernel_launch(void* const* d_in, const int* in_sizes, int n_in,
                              void* d_out, int out_size) {
    const float* q = (const float*)d_in[0];
    const float* k = (const float*)d_in[1];
    const int N = in_sizes[0] / D;          // 8192
    float* out = (float*)d_out;

    normalize_kernel<<<2 * N / 16, 256>>>(q, k, N, out);

    size_t smem = DATA_OFF + (size_t)3 * TILE_B;
    cudaFuncSetAttribute(infonce_kernel,
                         cudaFuncAttributeMaxDynamicSharedMemorySize, (int)smem);
    infonce_kernel<<<GRID_SZ, THREADS, smem>>>(out);
}